// round 4
// baseline (speedup 1.0000x reference)
#include <cuda_runtime.h>

#define HEADS 8
#define CH 32
#define NMAX 50000
#define EMAX 400000

__device__ float g_rinv[NMAX * HEADS];   // per (node,head) inverse RMS of k
__device__ int   g_rowptr[NMAX + 1];     // per-destination segment starts

__device__ __forceinline__ float warp_sum(float v) {
#pragma unroll
    for (int o = 16; o; o >>= 1) v += __shfl_xor_sync(0xffffffffu, v, o);
    return v;
}

// ---------------------------------------------------------------------------
// Kernel 1: rinv[row] = rsqrt(mean(k_row^2) + eps) — one THREAD per row,
// 8x float4 loads, in-thread sum (no shuffles). L1 absorbs the 8x line reuse.
// ---------------------------------------------------------------------------
__global__ void rinv_kernel(const float4* __restrict__ k4, int nrows) {
    int row = blockIdx.x * blockDim.x + threadIdx.x;
    if (row >= nrows) return;
    const float4* p = k4 + row * (CH / 4);
    float s = 0.0f;
#pragma unroll
    for (int i = 0; i < CH / 4; i++) {
        float4 a = p[i];
        s += a.x * a.x + a.y * a.y + a.z * a.z + a.w * a.w;
    }
    g_rinv[row] = rsqrtf(s * (1.0f / CH) + 1e-6f);
}

// ---------------------------------------------------------------------------
// Kernel 2: row_ptr[d] = lower_bound(edge_dst, d)
// ---------------------------------------------------------------------------
__global__ void rowptr_kernel(const int* __restrict__ dst, int E, int N) {
    int d = blockIdx.x * blockDim.x + threadIdx.x;
    if (d > N) return;
    int lo = 0, hi = E;
    while (lo < hi) {
        int mid = (lo + hi) >> 1;
        if (dst[mid] < d) lo = mid + 1; else hi = mid;
    }
    g_rowptr[d] = lo;
}

// ---------------------------------------------------------------------------
// Kernel 3: fused gather + dot + segment softmax (no running max — scores are
// O(8) so exp is safe; removes the serial rescale chain entirely).
//   block = dst, warp = head, lane = channel
// ---------------------------------------------------------------------------
__global__ void attn_kernel(const float* __restrict__ q,
                            const float* __restrict__ k,
                            const float* __restrict__ v,
                            const float* __restrict__ e,
                            const float* __restrict__ wq,
                            const float* __restrict__ wk,
                            const int*   __restrict__ src,
                            float* __restrict__ out) {
    const int d    = blockIdx.x;
    const int h    = threadIdx.x >> 5;
    const int lane = threadIdx.x & 31;

    const int start = g_rowptr[d];
    const int end   = g_rowptr[d + 1];

    // inline RMSNorm of q row
    float qx = q[(d * HEADS + h) * CH + lane];
    float ss = warp_sum(qx * qx);
    float qn = qx * rsqrtf(ss * (1.0f / CH) + 1e-6f) * wq[lane];

    const float scale = 0.1767766952966369f;  // 1/sqrt(32)
    const float wkl   = wk[lane];
    const int   hoff  = h * CH + lane;

    // 4 independent accumulator sets — reduction FMAs pipeline
    float l0 = 0.f, l1 = 0.f, l2 = 0.f, l3 = 0.f;
    float a0 = 0.f, a1 = 0.f, a2 = 0.f, a3 = 0.f;

    int eid = start;
    for (; eid + 4 <= end; eid += 4) {
        int s0 = src[eid + 0];
        int s1 = src[eid + 1];
        int s2 = src[eid + 2];
        int s3 = src[eid + 3];

        float e0 = __ldcs(&e[(eid + 0) * HEADS * CH + hoff]);
        float e1 = __ldcs(&e[(eid + 1) * HEADS * CH + hoff]);
        float e2 = __ldcs(&e[(eid + 2) * HEADS * CH + hoff]);
        float e3 = __ldcs(&e[(eid + 3) * HEADS * CH + hoff]);

        float r0 = g_rinv[s0 * HEADS + h] * wkl;
        float r1 = g_rinv[s1 * HEADS + h] * wkl;
        float r2 = g_rinv[s2 * HEADS + h] * wkl;
        float r3 = g_rinv[s3 * HEADS + h] * wkl;

        float k0 = k[s0 * HEADS * CH + hoff];
        float k1 = k[s1 * HEADS * CH + hoff];
        float k2 = k[s2 * HEADS * CH + hoff];
        float k3 = k[s3 * HEADS * CH + hoff];
        float v0 = v[s0 * HEADS * CH + hoff];
        float v1 = v[s1 * HEADS * CH + hoff];
        float v2 = v[s2 * HEADS * CH + hoff];
        float v3 = v[s3 * HEADS * CH + hoff];

        float d0 = qn * fmaf(k0, r0, e0);
        float d1 = qn * fmaf(k1, r1, e1);
        float d2 = qn * fmaf(k2, r2, e2);
        float d3 = qn * fmaf(k3, r3, e3);
#pragma unroll
        for (int o = 16; o; o >>= 1) {
            d0 += __shfl_xor_sync(0xffffffffu, d0, o);
            d1 += __shfl_xor_sync(0xffffffffu, d1, o);
            d2 += __shfl_xor_sync(0xffffffffu, d2, o);
            d3 += __shfl_xor_sync(0xffffffffu, d3, o);
        }
        // independent exp + accumulate (no cross-edge dependency)
        float p0 = __expf(d0 * scale);
        float p1 = __expf(d1 * scale);
        float p2 = __expf(d2 * scale);
        float p3 = __expf(d3 * scale);
        l0 += p0; l1 += p1; l2 += p2; l3 += p3;
        a0 = fmaf(p0, v0 + e0, a0);
        a1 = fmaf(p1, v1 + e1, a1);
        a2 = fmaf(p2, v2 + e2, a2);
        a3 = fmaf(p3, v3 + e3, a3);
    }

    for (; eid < end; eid++) {
        int   s  = src[eid];
        float ec = __ldcs(&e[eid * HEADS * CH + hoff]);
        float rr = g_rinv[s * HEADS + h] * wkl;
        float kc = k[s * HEADS * CH + hoff];
        float vc = v[s * HEADS * CH + hoff];
        float dd = warp_sum(qn * fmaf(kc, rr, ec));
        float p  = __expf(dd * scale);
        l0 += p;
        a0 = fmaf(p, vc + ec, a0);
    }

    float l   = (l0 + l1) + (l2 + l3);
    float acc = (a0 + a1) + (a2 + a3);
    out[(d * HEADS + h) * CH + lane] = (l > 0.0f) ? acc / l : 0.0f;
}

// ---------------------------------------------------------------------------
extern "C" void kernel_launch(void* const* d_in, const int* in_sizes, int n_in,
                              void* d_out, int out_size) {
    const float* q    = (const float*)d_in[0];
    const float* k    = (const float*)d_in[1];
    const float* v    = (const float*)d_in[2];
    const float* e    = (const float*)d_in[3];
    const float* wq   = (const float*)d_in[4];
    const float* wk   = (const float*)d_in[5];
    const int*   esrc = (const int*)d_in[6];
    const int*   edst = (const int*)d_in[7];

    const int N = in_sizes[0] / (HEADS * CH);
    const int E = in_sizes[6];
    const int nrows = N * HEADS;

    rinv_kernel<<<(nrows + 255) / 256, 256>>>((const float4*)k, nrows);
    rowptr_kernel<<<(N + 256) / 256, 256>>>(edst, E, N);
    attn_kernel<<<N, 256>>>(q, k, v, e, wq, wk, esrc, (float*)d_out);
}

// round 5
// speedup vs baseline: 1.3247x; 1.3247x over previous
#include <cuda_runtime.h>

#define HEADS 8
#define CH 32
#define CH4 8              // float4 chunks per row
#define NMAX 50000
#define EMAX 400000

__device__ float4 g_kn4[NMAX * HEADS * CH4];  // RMSNorm'd K, float4 layout
__device__ int    g_rowptr[NMAX + 1];

// ---------------------------------------------------------------------------
// Kernel 1: kn = RMSNorm(k)*w_k — warp handles 4 rows; 8-lane group per row,
// one float4 per lane. 1 LDG.128 + 1 STG.128 + 3 SHFL per 4 rows.
// ---------------------------------------------------------------------------
__global__ void kn_kernel(const float4* __restrict__ k4,
                          const float4* __restrict__ w4,
                          int nrows) {
    int warp = blockIdx.x * (blockDim.x >> 5) + (threadIdx.x >> 5);
    int lane = threadIdx.x & 31;
    int g = lane >> 3;           // row within warp's group of 4
    int i = lane & 7;            // float4 chunk within row
    int row = warp * 4 + g;
    if (row >= nrows) return;

    float4 x = k4[row * CH4 + i];
    float s = x.x * x.x + x.y * x.y + x.z * x.z + x.w * x.w;
#pragma unroll
    for (int o = 1; o <= 4; o <<= 1) s += __shfl_xor_sync(0xffffffffu, s, o);
    float r = rsqrtf(s * (1.0f / CH) + 1e-6f);
    float4 w = w4[i];
    float4 y;
    y.x = x.x * r * w.x; y.y = x.y * r * w.y;
    y.z = x.z * r * w.z; y.w = x.w * r * w.w;
    g_kn4[row * CH4 + i] = y;
}

// ---------------------------------------------------------------------------
// Kernel 2: row_ptr[d] = lower_bound(edge_dst, d)
// ---------------------------------------------------------------------------
__global__ void rowptr_kernel(const int* __restrict__ dst, int E, int N) {
    int d = blockIdx.x * blockDim.x + threadIdx.x;
    if (d > N) return;
    int lo = 0, hi = E;
    while (lo < hi) {
        int mid = (lo + hi) >> 1;
        if (dst[mid] < d) lo = mid + 1; else hi = mid;
    }
    g_rowptr[d] = lo;
}

// ---------------------------------------------------------------------------
// Kernel 3: block = dst, warp = head.
//   lane = g*8+i : group g (0..3) = edge slot, i (0..7) = float4 chunk.
//   4 edges per iteration; branchless tail via index clamp + p-masking.
//   No running max (scores are O(8); exp cannot overflow fp32).
// ---------------------------------------------------------------------------
__global__ void attn_kernel(const float4* __restrict__ q4,
                            const float4* __restrict__ v4,
                            const float4* __restrict__ e4,
                            const float4* __restrict__ wq4,
                            const int*    __restrict__ src,
                            float4* __restrict__ out4) {
    const int d    = blockIdx.x;
    const int h    = threadIdx.x >> 5;
    const int lane = threadIdx.x & 31;
    const int g    = lane >> 3;
    const int i    = lane & 7;

    const int start = g_rowptr[d];
    const int end   = g_rowptr[d + 1];

    // RMSNorm(q) — each 8-lane group holds the full row (groups redundant)
    float4 qv = q4[(d * HEADS + h) * CH4 + i];
    float ss = qv.x * qv.x + qv.y * qv.y + qv.z * qv.z + qv.w * qv.w;
#pragma unroll
    for (int o = 1; o <= 4; o <<= 1) ss += __shfl_xor_sync(0xffffffffu, ss, o);
    float rq = rsqrtf(ss * (1.0f / CH) + 1e-6f);
    float4 w = wq4[i];
    float4 qn;
    qn.x = qv.x * rq * w.x; qn.y = qv.y * rq * w.y;
    qn.z = qv.z * rq * w.z; qn.w = qv.w * rq * w.w;

    const float scale = 0.1767766952966369f;  // 1/sqrt(32)

    float  l = 0.0f;
    float4 acc = make_float4(0.f, 0.f, 0.f, 0.f);

#pragma unroll 2
    for (int eid = start; eid < end; eid += 4) {
        int  my_e  = eid + g;
        bool valid = my_e < end;
        int  ce    = valid ? my_e : end - 1;   // clamp (loop body implies end>start)
        int  s     = src[ce];

        float4 ev = __ldcs(&e4[((size_t)ce * HEADS + h) * CH4 + i]);
        float4 kn = g_kn4[(s * HEADS + h) * CH4 + i];
        float4 vv = v4[(s * HEADS + h) * CH4 + i];

        // partial dot of qn · (kn + e) over this lane's 4 channels
        float p = qn.x * (kn.x + ev.x);
        p = fmaf(qn.y, kn.y + ev.y, p);
        p = fmaf(qn.z, kn.z + ev.z, p);
        p = fmaf(qn.w, kn.w + ev.w, p);
        // reduce within 8-lane group (handles all 4 groups at once)
#pragma unroll
        for (int o = 1; o <= 4; o <<= 1) p += __shfl_xor_sync(0xffffffffu, p, o);

        float pe = valid ? __expf(p * scale) : 0.0f;

        l += pe;
        acc.x = fmaf(pe, vv.x + ev.x, acc.x);
        acc.y = fmaf(pe, vv.y + ev.y, acc.y);
        acc.z = fmaf(pe, vv.z + ev.z, acc.z);
        acc.w = fmaf(pe, vv.w + ev.w, acc.w);
    }

    // combine the 4 edge-groups (lanes with equal i)
#pragma unroll
    for (int o = 8; o <= 16; o <<= 1) {
        l     += __shfl_xor_sync(0xffffffffu, l, o);
        acc.x += __shfl_xor_sync(0xffffffffu, acc.x, o);
        acc.y += __shfl_xor_sync(0xffffffffu, acc.y, o);
        acc.z += __shfl_xor_sync(0xffffffffu, acc.z, o);
        acc.w += __shfl_xor_sync(0xffffffffu, acc.w, o);
    }

    if (g == 0) {
        float inv = (l > 0.0f) ? 1.0f / l : 0.0f;
        float4 o;
        o.x = acc.x * inv; o.y = acc.y * inv;
        o.z = acc.z * inv; o.w = acc.w * inv;
        out4[(d * HEADS + h) * CH4 + i] = o;
    }
}

// ---------------------------------------------------------------------------
extern "C" void kernel_launch(void* const* d_in, const int* in_sizes, int n_in,
                              void* d_out, int out_size) {
    const float* q    = (const float*)d_in[0];
    const float* k    = (const float*)d_in[1];
    const float* v    = (const float*)d_in[2];
    const float* e    = (const float*)d_in[3];
    const float* wq   = (const float*)d_in[4];
    const float* wk   = (const float*)d_in[5];
    const int*   esrc = (const int*)d_in[6];
    const int*   edst = (const int*)d_in[7];

    const int N = in_sizes[0] / (HEADS * CH);
    const int E = in_sizes[6];
    const int nrows = N * HEADS;

    int kn_warps  = (nrows + 3) / 4;
    int kn_blocks = (kn_warps + 7) / 8;
    kn_kernel<<<kn_blocks, 256>>>((const float4*)k, (const float4*)wk, nrows);
    rowptr_kernel<<<(N + 256) / 256, 256>>>(edst, E, N);
    attn_kernel<<<N, 256>>>((const float4*)q, (const float4*)v,
                            (const float4*)e, (const float4*)wq,
                            esrc, (float4*)d_out);
}